// round 13
// baseline (speedup 1.0000x reference)
#include <cuda_runtime.h>
#include <cuda_fp16.h>
#include <cstdint>

#define NN 32
#define CC 64
#define TT 512
#define VV 25
#define HH 3
#define TB 8
#define TOTAL (NN*CC*TT*VV)     // 26214400
#define CNT_F (NN*TT*VV)        // 409600

// smem layout (bytes)
#define XS 264                  // X row stride in halves: 8*32 + 8 pad
#define XH_B 0                  // half [64][264]   = 33792 B
#define AH_B 33792              // half [96][40]    = 7680 B
#define ST_B 41472              // float [128]      = 512 B
#define A24_B 41984             // float [3][32]    = 384 B
#define SM_BYTES 42368

__device__ uint4  g_conv4[TOTAL/8];  // conv output as fp16 (uint4 backing, 16B aligned)
__device__ uint4  g_Wf[HH*4*4*32];   // per-lane W a-fragments, LDG.128-ready
__device__ float  g_stats[128];
__device__ float  g_scale[CC];
__device__ float  g_shift[CC];

__device__ __forceinline__ uint32_t smem_u32(const void* p) {
    uint32_t a;
    asm("{ .reg .u64 t; cvta.to.shared.u64 t, %1; cvt.u32.u64 %0, t; }" : "=r"(a) : "l"(p));
    return a;
}
__device__ __forceinline__ void ldmx4t(uint32_t& r0, uint32_t& r1, uint32_t& r2, uint32_t& r3, uint32_t a) {
    asm volatile("ldmatrix.sync.aligned.m8n8.x4.trans.shared.b16 {%0,%1,%2,%3},[%4];"
                 : "=r"(r0), "=r"(r1), "=r"(r2), "=r"(r3) : "r"(a));
}
__device__ __forceinline__ void ldmx2(uint32_t& r0, uint32_t& r1, uint32_t a) {
    asm volatile("ldmatrix.sync.aligned.m8n8.x2.shared.b16 {%0,%1},[%2];"
                 : "=r"(r0), "=r"(r1) : "r"(a));
}
__device__ __forceinline__ void mma16(float* c, const uint32_t* a, uint32_t b0, uint32_t b1) {
    asm volatile("mma.sync.aligned.m16n8k16.row.col.f32.f16.f16.f32 "
        "{%0,%1,%2,%3},{%4,%5,%6,%7},{%8,%9},{%0,%1,%2,%3};"
        : "+f"(c[0]), "+f"(c[1]), "+f"(c[2]), "+f"(c[3])
        : "r"(a[0]), "r"(a[1]), "r"(a[2]), "r"(a[3]), "r"(b0), "r"(b1));
}
__device__ __forceinline__ uint32_t h2u(__half2 h) { return *reinterpret_cast<uint32_t*>(&h); }

// ---------------------------------------------------------------------------
// prep: bake W into per-lane mma a-fragment order (same as R12), zero stats.
// ---------------------------------------------------------------------------
__global__ void prep_k(const float* __restrict__ W) {
    int i = blockIdx.x * blockDim.x + threadIdx.x;
    if (i < HH*4*4*32*4) {
        int r    = i & 3;
        int lane = (i >> 2) & 31;
        int kk   = (i >> 7) & 3;
        int w4   = (i >> 9) & 3;
        int h    = i >> 11;
        int grp = lane >> 2, tig = lane & 3;
        int o = w4*16 + grp + (r & 1)*8;
        int c = kk*16 + ((r & 2) ? 8 : 0) + tig*2;
        const float* wp = W + (h*CC + o)*CC + c;
        reinterpret_cast<uint32_t*>(g_Wf)[i] = h2u(__floats2half2_rn(wp[0], wp[1]));
    }
    if (i < 128) g_stats[i] = 0.f;
}

// ---------------------------------------------------------------------------
// conv: fp16 mma.m16n8k16, fp32 accum. CTA = (n, 8 t's), 128 thr, 4 CTAs/SM.
// stage1: Y[o, 32t+u] = W_h[o,c] @ X[c, 32t+u]   (W frags via LDG.128)
// stage2: OUT[o, v<24] via mma (nv=0..2); v=24 via fp32 scalar correction.
// conv output stored as fp16.
// ---------------------------------------------------------------------------
__global__ __launch_bounds__(128, 4) void conv_mma(const float* __restrict__ x,
                                                   const float* __restrict__ A) {
    extern __shared__ char sm[];
    __half* Xh   = (__half*)(sm + XH_B);
    __half* Ah   = (__half*)(sm + AH_B);
    float*  St   = (float*)(sm + ST_B);
    float*  A24f = (float*)(sm + A24_B);
    __half* convh = (__half*)g_conv4;

    const uint32_t smb = smem_u32(sm);
    const int tid  = threadIdx.x;
    const int warp = tid >> 5, lane = tid & 31;
    const int grp  = lane >> 2, tig = lane & 3;
    const int n    = blockIdx.x >> 6;            // 64 t-blocks per n
    const int t0   = (blockIdx.x & 63) * TB;

    St[tid] = 0.f;

    // --- A smem: [3*32][40] halves, zero-padded beyond 25x25 ---
    for (int i = tid; i < HH*32*32; i += 128) {
        int h = i >> 10, rem = i & 1023;
        int v = rem >> 5, u = rem & 31;
        float val = (v < VV && u < VV) ? A[(h*VV + v)*VV + u] : 0.f;
        Ah[(h*32 + v)*40 + u] = __float2half_rn(val);
    }
    // --- A row 24 in fp32: A24f[h][u] ---
    if (tid < HH*32) {
        int h = tid >> 5, u = tid & 31;
        A24f[h*32 + u] = (u < VV) ? A[(h*VV + 24)*VV + u] : 0.f;
    }
    // --- X pad: cols 32t+25..32t+31 zero, all 64 rows ---
    for (int i = tid; i < 64*56; i += 128) {
        int r = i / 56, k = i - r*56;
        int col = 32*(k/7) + 25 + (k%7);
        Xh[r*XS + col] = __float2half(0.f);
    }
    // --- X fill natural: Xh[c][32*(s/25) + s%25] ---
    {
        const float4* x4 = reinterpret_cast<const float4*>(x);
        for (int i = tid; i < CC*50; i += 128) {
            int c = i / 50, q = i - c*50;
            unsigned base = ((unsigned)(n*CC + c)*TT + t0)*VV;
            float4 v = x4[(base >> 2) + q];
            float vv[4] = {v.x, v.y, v.z, v.w};
            #pragma unroll
            for (int e = 0; e < 4; ++e) {
                int s = q*4 + e;
                int col = (s/25)*32 + (s - (s/25)*25);
                Xh[c*XS + col] = __float2half_rn(vv[e]);
            }
        }
    }
    __syncthreads();

    const int q4 = lane >> 3, r8 = lane & 7;
    const int brow = lane & 7;
    const int bcol8 = (lane & 8) ? 8 : 0;
    const uint32_t xlane = (uint32_t)((r8 + ((q4 & 1) ? 8 : 0)) * XS + ((q4 & 2) ? 8 : 0)) * 2;

    const uint4* wbase = g_Wf + warp*4*32 + lane;

    float st1a = 0.f, st2a = 0.f, st1b = 0.f, st2b = 0.f;
    const int r0 = warp*16 + grp, r1 = r0 + 8;

    for (int t = 0; t < TB; ++t) {
        // ---- X b-fragments for this t (32 regs) ----
        uint32_t xf[4][2][4];
        #pragma unroll
        for (int kk = 0; kk < 4; ++kk)
            #pragma unroll
            for (int jp = 0; jp < 2; ++jp) {
                uint32_t off = xlane + (uint32_t)((16*kk)*XS + 32*t + 16*jp) * 2;
                ldmx4t(xf[kk][jp][0], xf[kk][jp][1], xf[kk][jp][2], xf[kk][jp][3],
                       smb + XH_B + off);
            }

        float OUT[3][4];
        #pragma unroll
        for (int nv = 0; nv < 3; ++nv)
            #pragma unroll
            for (int e = 0; e < 4; ++e) OUT[nv][e] = 0.f;
        float p0acc = 0.f, p1acc = 0.f;      // v=24 partials (rows r0, r1)

        #pragma unroll
        for (int h = 0; h < HH; ++h) {
            // stage-2 B fragments for this head, nv=0..2 (12 regs)
            uint32_t B2[3][2][2];
            #pragma unroll
            for (int nv = 0; nv < 3; ++nv)
                #pragma unroll
                for (int kp = 0; kp < 2; ++kp) {
                    uint32_t off = (uint32_t)(((h*32 + 8*nv + brow)*40) + kp*16 + bcol8) * 2;
                    ldmx2(B2[nv][kp][0], B2[nv][kp][1], smb + AH_B + off);
                }

            // stage 1
            float Y[4][4];
            #pragma unroll
            for (int j = 0; j < 4; ++j)
                #pragma unroll
                for (int e = 0; e < 4; ++e) Y[j][e] = 0.f;

            #pragma unroll
            for (int kk = 0; kk < 4; ++kk) {
                uint4 wv = __ldg(wbase + (h*16 + kk)*32);
                uint32_t whf[4] = {wv.x, wv.y, wv.z, wv.w};
                #pragma unroll
                for (int j = 0; j < 4; ++j) {
                    int jp = j >> 1, ix = (j & 1) * 2;
                    mma16(Y[j], whf, xf[kk][jp][ix], xf[kk][jp][ix + 1]);
                }
            }

            // stage 2 mma (v = 0..23)
            #pragma unroll
            for (int kp = 0; kp < 2; ++kp) {
                uint32_t ah[4];
                #pragma unroll
                for (int i = 0; i < 4; ++i) {
                    const float* yp = Y[2*kp + (i >> 1)];
                    float p  = yp[(i & 1) ? 2 : 0];
                    float qv = yp[(i & 1) ? 3 : 1];
                    ah[i] = h2u(__floats2half2_rn(p, qv));
                }
                #pragma unroll
                for (int nv = 0; nv < 3; ++nv)
                    mma16(OUT[nv], ah, B2[nv][kp][0], B2[nv][kp][1]);
            }

            // v=24 scalar correction (fp32): lane holds u = 8j+2tig(+1)
            #pragma unroll
            for (int j = 0; j < 4; ++j) {
                float2 a = *reinterpret_cast<const float2*>(
                    sm + A24_B + (((h*32) + 8*j + 2*tig) << 2));
                p0acc += Y[j][0]*a.x + Y[j][1]*a.y;
                p1acc += Y[j][2]*a.x + Y[j][3]*a.y;
            }
        }

        // reduce v=24 partials across the 4 tig lanes
        p0acc += __shfl_xor_sync(0xFFFFFFFFu, p0acc, 1);
        p0acc += __shfl_xor_sync(0xFFFFFFFFu, p0acc, 2);
        p1acc += __shfl_xor_sync(0xFFFFFFFFu, p1acc, 1);
        p1acc += __shfl_xor_sync(0xFFFFFFFFu, p1acc, 2);

        // per-t epilogue: fp16 stores, register stats
        unsigned base0 = ((unsigned)(n*CC + r0)*TT + t0 + t)*VV;
        unsigned base1 = ((unsigned)(n*CC + r1)*TT + t0 + t)*VV;
        #pragma unroll
        for (int nv = 0; nv < 3; ++nv) {
            int v0 = 8*nv + 2*tig;                        // always <= 22
            float a0 = OUT[nv][0], b0 = OUT[nv][2];
            float a1 = OUT[nv][1], b1 = OUT[nv][3];
            convh[base0 + v0]     = __float2half_rn(a0);
            convh[base0 + v0 + 1] = __float2half_rn(a1);
            convh[base1 + v0]     = __float2half_rn(b0);
            convh[base1 + v0 + 1] = __float2half_rn(b1);
            st1a += a0 + a1; st2a += a0*a0 + a1*a1;
            st1b += b0 + b1; st2b += b0*b0 + b1*b1;
        }
        if (tig == 0) {
            convh[base0 + 24] = __float2half_rn(p0acc);
            convh[base1 + 24] = __float2half_rn(p1acc);
            st1a += p0acc; st2a += p0acc*p0acc;
            st1b += p1acc; st2b += p1acc*p1acc;
        }
        p0acc = 0.f; p1acc = 0.f;
    }

    // --- stats: smem reduce, one global atomic per tid ---
    atomicAdd(&St[r0],      st1a);
    atomicAdd(&St[64 + r0], st2a);
    atomicAdd(&St[r1],      st1b);
    atomicAdd(&St[64 + r1], st2b);
    __syncthreads();
    atomicAdd(&g_stats[tid], St[tid]);
}

// ---------------------------------------------------------------------------
__global__ void stats_k(const float* __restrict__ gamma, const float* __restrict__ beta) {
    int o = threadIdx.x;
    if (o < CC) {
        const float inv = 1.f / (float)CNT_F;
        float mean = g_stats[o] * inv;
        float var  = g_stats[64 + o] * inv - mean*mean;
        float sc = gamma[o] * rsqrtf(var + 1e-5f);
        g_scale[o] = sc;
        g_shift[o] = beta[o] - mean*sc;
    }
}

// ---------------------------------------------------------------------------
// pass 2: out = relu(scale[c]*conv_fp16 + shift[c] + x), streaming
// ---------------------------------------------------------------------------
__global__ void bn_apply(const float4* __restrict__ xv, float4* __restrict__ ov) {
    const uint2* cv = reinterpret_cast<const uint2*>(g_conv4);
    const int n4 = TOTAL / 4;
    int stride = gridDim.x * blockDim.x;
    for (int i = blockIdx.x * blockDim.x + threadIdx.x; i < n4; i += stride) {
        int c = (i / 3200) & 63;
        float s  = __ldg(&g_scale[c]);
        float sh = __ldg(&g_shift[c]);
        uint2 cc = cv[i];
        float2 f01 = __half22float2(*reinterpret_cast<__half2*>(&cc.x));
        float2 f23 = __half22float2(*reinterpret_cast<__half2*>(&cc.y));
        float4 b = xv[i];
        float4 r;
        r.x = fmaxf(fmaf(s, f01.x, sh) + b.x, 0.f);
        r.y = fmaxf(fmaf(s, f01.y, sh) + b.y, 0.f);
        r.z = fmaxf(fmaf(s, f23.x, sh) + b.z, 0.f);
        r.w = fmaxf(fmaf(s, f23.y, sh) + b.w, 0.f);
        ov[i] = r;
    }
}

// ---------------------------------------------------------------------------
extern "C" void kernel_launch(void* const* d_in, const int* in_sizes, int n_in,
                              void* d_out, int out_size) {
    const float* x     = (const float*)d_in[0];
    const float* A     = (const float*)d_in[1];
    const float* W     = (const float*)d_in[2];
    // d_in[3] = b : cancels exactly under training-mode BatchNorm -> unused
    const float* gamma = (const float*)d_in[4];
    const float* beta  = (const float*)d_in[5];
    float* out = (float*)d_out;

    cudaFuncSetAttribute(conv_mma, cudaFuncAttributeMaxDynamicSharedMemorySize, SM_BYTES);

    prep_k<<<48, 256>>>(W);
    conv_mma<<<NN*(TT/TB), 128, SM_BYTES>>>(x, A);
    stats_k<<<1, 64>>>(gamma, beta);
    bn_apply<<<4096, 256>>>(reinterpret_cast<const float4*>(x),
                            reinterpret_cast<float4*>(out));
}

// round 14
// speedup vs baseline: 1.1842x; 1.1842x over previous
#include <cuda_runtime.h>
#include <cuda_fp16.h>
#include <cstdint>

#define NN 32
#define CC 64
#define TT 512
#define VV 25
#define HH 3
#define TB 8
#define TOTAL (NN*CC*TT*VV)     // 26214400
#define CNT_F (NN*TT*VV)        // 409600

// smem layout (bytes)
#define XS 264                  // X row stride in halves: 8*32 + 8 pad
#define XH_B 0                  // half [64][264]   = 33792 B
#define AH_B 33792              // half [96][40]    = 7680 B
#define ST_B 41472              // float [128]      = 512 B
#define SM_BYTES 41984

__device__ uint4  g_conv4[TOTAL/8];  // conv output as fp16
__device__ uint4  g_Wf[HH*4*4*32];   // per-lane W a-fragments, LDG.128-ready
__device__ float  g_stats[128];
__device__ float  g_scale[CC];
__device__ float  g_shift[CC];

__device__ __forceinline__ uint32_t smem_u32(const void* p) {
    uint32_t a;
    asm("{ .reg .u64 t; cvta.to.shared.u64 t, %1; cvt.u32.u64 %0, t; }" : "=r"(a) : "l"(p));
    return a;
}
__device__ __forceinline__ void ldmx4t(uint32_t& r0, uint32_t& r1, uint32_t& r2, uint32_t& r3, uint32_t a) {
    asm volatile("ldmatrix.sync.aligned.m8n8.x4.trans.shared.b16 {%0,%1,%2,%3},[%4];"
                 : "=r"(r0), "=r"(r1), "=r"(r2), "=r"(r3) : "r"(a));
}
__device__ __forceinline__ void ldmx2(uint32_t& r0, uint32_t& r1, uint32_t a) {
    asm volatile("ldmatrix.sync.aligned.m8n8.x2.shared.b16 {%0,%1},[%2];"
                 : "=r"(r0), "=r"(r1) : "r"(a));
}
__device__ __forceinline__ void mma16(float* c, const uint32_t* a, uint32_t b0, uint32_t b1) {
    asm volatile("mma.sync.aligned.m16n8k16.row.col.f32.f16.f16.f32 "
        "{%0,%1,%2,%3},{%4,%5,%6,%7},{%8,%9},{%0,%1,%2,%3};"
        : "+f"(c[0]), "+f"(c[1]), "+f"(c[2]), "+f"(c[3])
        : "r"(a[0]), "r"(a[1]), "r"(a[2]), "r"(a[3]), "r"(b0), "r"(b1));
}
__device__ __forceinline__ uint32_t h2u(__half2 h) { return *reinterpret_cast<uint32_t*>(&h); }

// ---------------------------------------------------------------------------
// prep: bake W into per-lane mma a-fragment order, zero stats.
// ---------------------------------------------------------------------------
__global__ void prep_k(const float* __restrict__ W) {
    int i = blockIdx.x * blockDim.x + threadIdx.x;
    if (i < HH*4*4*32*4) {
        int r    = i & 3;
        int lane = (i >> 2) & 31;
        int kk   = (i >> 7) & 3;
        int w4   = (i >> 9) & 3;
        int h    = i >> 11;
        int grp = lane >> 2, tig = lane & 3;
        int o = w4*16 + grp + (r & 1)*8;
        int c = kk*16 + ((r & 2) ? 8 : 0) + tig*2;
        const float* wp = W + (h*CC + o)*CC + c;
        reinterpret_cast<uint32_t*>(g_Wf)[i] = h2u(__floats2half2_rn(wp[0], wp[1]));
    }
    if (i < 128) g_stats[i] = 0.f;
}

// ---------------------------------------------------------------------------
// conv: fp16 mma.m16n8k16, fp32 accum. CTA = (n, 8 t's), 128 thr, 4 CTAs/SM.
// Identical to R12 except conv output stored as fp16.
// ---------------------------------------------------------------------------
__global__ __launch_bounds__(128, 4) void conv_mma(const float* __restrict__ x,
                                                   const float* __restrict__ A) {
    extern __shared__ char sm[];
    __half* Xh = (__half*)(sm + XH_B);
    __half* Ah = (__half*)(sm + AH_B);
    float*  St = (float*)(sm + ST_B);
    __half* convh = (__half*)g_conv4;

    const uint32_t smb = smem_u32(sm);
    const int tid  = threadIdx.x;
    const int warp = tid >> 5, lane = tid & 31;
    const int grp  = lane >> 2, tig = lane & 3;
    const int n    = blockIdx.x >> 6;            // 64 t-blocks per n
    const int t0   = (blockIdx.x & 63) * TB;

    St[tid] = 0.f;

    // --- A smem: [3*32][40] halves, zero-padded beyond 25x25 ---
    for (int i = tid; i < HH*32*32; i += 128) {
        int h = i >> 10, rem = i & 1023;
        int v = rem >> 5, u = rem & 31;
        float val = (v < VV && u < VV) ? A[(h*VV + v)*VV + u] : 0.f;
        Ah[(h*32 + v)*40 + u] = __float2half_rn(val);
    }
    // --- X pad: cols 32t+25..32t+31 zero, all 64 rows ---
    for (int i = tid; i < 64*56; i += 128) {
        int r = i / 56, k = i - r*56;
        int col = 32*(k/7) + 25 + (k%7);
        Xh[r*XS + col] = __float2half(0.f);
    }
    // --- X fill natural: Xh[c][32*(s/25) + s%25] from 200 contiguous floats/c ---
    {
        const float4* x4 = reinterpret_cast<const float4*>(x);
        for (int i = tid; i < CC*50; i += 128) {
            int c = i / 50, q = i - c*50;
            unsigned base = ((unsigned)(n*CC + c)*TT + t0)*VV;   // divisible by 4
            float4 v = x4[(base >> 2) + q];
            float vv[4] = {v.x, v.y, v.z, v.w};
            #pragma unroll
            for (int e = 0; e < 4; ++e) {
                int s = q*4 + e;
                int col = (s/25)*32 + (s - (s/25)*25);
                Xh[c*XS + col] = __float2half_rn(vv[e]);
            }
        }
    }
    __syncthreads();

    // ldmatrix address components
    const int q4 = lane >> 3, r8 = lane & 7;
    const int brow = lane & 7;                     // for A ldmx2 (non-trans)
    const int bcol8 = (lane & 8) ? 8 : 0;
    const uint32_t xlane = (uint32_t)((r8 + ((q4 & 1) ? 8 : 0)) * XS + ((q4 & 2) ? 8 : 0)) * 2;

    // per-warp W fragment base (uint4 index)
    const uint4* wbase = g_Wf + warp*4*32 + lane;   // + h*4*4*32 + kk*32

    float st1a = 0.f, st2a = 0.f, st1b = 0.f, st2b = 0.f;
    const int r0 = warp*16 + grp, r1 = r0 + 8;

    for (int t = 0; t < TB; ++t) {
        // ---- X b-fragments for this t, ALL kk and j (32 regs) ----
        uint32_t xf[4][2][4];
        #pragma unroll
        for (int kk = 0; kk < 4; ++kk)
            #pragma unroll
            for (int jp = 0; jp < 2; ++jp) {
                uint32_t off = xlane + (uint32_t)((16*kk)*XS + 32*t + 16*jp) * 2;
                ldmx4t(xf[kk][jp][0], xf[kk][jp][1], xf[kk][jp][2], xf[kk][jp][3],
                       smb + XH_B + off);
            }

        float OUT[4][4];
        #pragma unroll
        for (int nv = 0; nv < 4; ++nv)
            #pragma unroll
            for (int e = 0; e < 4; ++e) OUT[nv][e] = 0.f;

        #pragma unroll
        for (int h = 0; h < HH; ++h) {
            // stage-2 B fragments for this head (16 regs)
            uint32_t B2[4][2][2];
            #pragma unroll
            for (int nv = 0; nv < 4; ++nv)
                #pragma unroll
                for (int kp = 0; kp < 2; ++kp) {
                    uint32_t off = (uint32_t)(((h*32 + 8*nv + brow)*40) + kp*16 + bcol8) * 2;
                    ldmx2(B2[nv][kp][0], B2[nv][kp][1], smb + AH_B + off);
                }

            // stage 1
            float Y[4][4];
            #pragma unroll
            for (int j = 0; j < 4; ++j)
                #pragma unroll
                for (int e = 0; e < 4; ++e) Y[j][e] = 0.f;

            #pragma unroll
            for (int kk = 0; kk < 4; ++kk) {
                uint4 wv = __ldg(wbase + (h*16 + kk)*32);
                uint32_t whf[4] = {wv.x, wv.y, wv.z, wv.w};
                #pragma unroll
                for (int j = 0; j < 4; ++j) {
                    int jp = j >> 1, ix = (j & 1) * 2;
                    mma16(Y[j], whf, xf[kk][jp][ix], xf[kk][jp][ix + 1]);
                }
            }

            // stage 2: in-register Y -> a-frags, accumulate OUT
            #pragma unroll
            for (int kp = 0; kp < 2; ++kp) {
                uint32_t ah[4];
                #pragma unroll
                for (int i = 0; i < 4; ++i) {
                    const float* yp = Y[2*kp + (i >> 1)];
                    float p  = yp[(i & 1) ? 2 : 0];
                    float qv = yp[(i & 1) ? 3 : 1];
                    ah[i] = h2u(__floats2half2_rn(p, qv));
                }
                #pragma unroll
                for (int nv = 0; nv < 4; ++nv)
                    mma16(OUT[nv], ah, B2[nv][kp][0], B2[nv][kp][1]);
            }
        }

        // per-t epilogue: fp16 scalar stores (warp-private rows), register stats
        unsigned base0 = ((unsigned)(n*CC + r0)*TT + t0 + t)*VV;
        unsigned base1 = ((unsigned)(n*CC + r1)*TT + t0 + t)*VV;
        #pragma unroll
        for (int nv = 0; nv < 4; ++nv) {
            int v0 = 8*nv + 2*tig;
            if (v0 < VV) {
                float a0 = OUT[nv][0], b0 = OUT[nv][2];
                convh[base0 + v0] = __float2half_rn(a0);
                convh[base1 + v0] = __float2half_rn(b0);
                st1a += a0; st2a += a0*a0;
                st1b += b0; st2b += b0*b0;
                if (v0 + 1 < VV) {
                    float a1 = OUT[nv][1], b1 = OUT[nv][3];
                    convh[base0 + v0 + 1] = __float2half_rn(a1);
                    convh[base1 + v0 + 1] = __float2half_rn(b1);
                    st1a += a1; st2a += a1*a1;
                    st1b += b1; st2b += b1*b1;
                }
            }
        }
    }

    // --- stats: smem reduce, one global atomic per tid ---
    atomicAdd(&St[r0],      st1a);
    atomicAdd(&St[64 + r0], st2a);
    atomicAdd(&St[r1],      st1b);
    atomicAdd(&St[64 + r1], st2b);
    __syncthreads();
    atomicAdd(&g_stats[tid], St[tid]);
}

// ---------------------------------------------------------------------------
__global__ void stats_k(const float* __restrict__ gamma, const float* __restrict__ beta) {
    int o = threadIdx.x;
    if (o < CC) {
        const float inv = 1.f / (float)CNT_F;
        float mean = g_stats[o] * inv;
        float var  = g_stats[64 + o] * inv - mean*mean;
        float sc = gamma[o] * rsqrtf(var + 1e-5f);
        g_scale[o] = sc;
        g_shift[o] = beta[o] - mean*sc;
    }
}

// ---------------------------------------------------------------------------
// pass 2: out = relu(scale[c]*conv_fp16 + shift[c] + x), streaming
// ---------------------------------------------------------------------------
__global__ void bn_apply(const float4* __restrict__ xv, float4* __restrict__ ov) {
    const uint2* cv = reinterpret_cast<const uint2*>(g_conv4);
    const int n4 = TOTAL / 4;
    int stride = gridDim.x * blockDim.x;
    for (int i = blockIdx.x * blockDim.x + threadIdx.x; i < n4; i += stride) {
        int c = (i / 3200) & 63;
        float s  = __ldg(&g_scale[c]);
        float sh = __ldg(&g_shift[c]);
        uint2 cc = cv[i];
        float2 f01 = __half22float2(*reinterpret_cast<__half2*>(&cc.x));
        float2 f23 = __half22float2(*reinterpret_cast<__half2*>(&cc.y));
        float4 b = xv[i];
        float4 r;
        r.x = fmaxf(fmaf(s, f01.x, sh) + b.x, 0.f);
        r.y = fmaxf(fmaf(s, f01.y, sh) + b.y, 0.f);
        r.z = fmaxf(fmaf(s, f23.x, sh) + b.z, 0.f);
        r.w = fmaxf(fmaf(s, f23.y, sh) + b.w, 0.f);
        ov[i] = r;
    }
}

// ---------------------------------------------------------------------------
extern "C" void kernel_launch(void* const* d_in, const int* in_sizes, int n_in,
                              void* d_out, int out_size) {
    const float* x     = (const float*)d_in[0];
    const float* A     = (const float*)d_in[1];
    const float* W     = (const float*)d_in[2];
    // d_in[3] = b : cancels exactly under training-mode BatchNorm -> unused
    const float* gamma = (const float*)d_in[4];
    const float* beta  = (const float*)d_in[5];
    float* out = (float*)d_out;

    cudaFuncSetAttribute(conv_mma, cudaFuncAttributeMaxDynamicSharedMemorySize, SM_BYTES);

    prep_k<<<48, 256>>>(W);
    conv_mma<<<NN*(TT/TB), 128, SM_BYTES>>>(x, A);
    stats_k<<<1, 64>>>(gamma, beta);
    bn_apply<<<4096, 256>>>(reinterpret_cast<const float4*>(x),
                            reinterpret_cast<float4*>(out));
}

// round 15
// speedup vs baseline: 1.5676x; 1.3237x over previous
#include <cuda_runtime.h>
#include <cuda_fp16.h>
#include <cstdint>

#define NN 32
#define CC 64
#define TT 512
#define VV 25
#define HH 3
#define TB 8
#define TOTAL (NN*CC*TT*VV)     // 26214400
#define NROWS (NN*CC*TT)        // 1048576 rows of 25 (dense) / 32 (padded)
#define CNT_F (NN*TT*VV)        // 409600

// smem layout (bytes)
#define XS 264                  // X row stride in halves: 8*32 + 8 pad
#define XH_B 0                  // half [64][264]   = 33792 B
#define AH_B 33792              // half [96][40]    = 7680 B
#define ST_B 41472              // float [128]      = 512 B
#define SM_BYTES 41984

__device__ __half2 g_convP[NROWS*16];   // conv out fp16, rows padded to 32 halves (64B)
__device__ uint4   g_Wf[HH*4*4*32];     // per-lane W a-fragments, LDG.128-ready
__device__ float   g_stats[128];
__device__ float   g_scale[CC];
__device__ float   g_shift[CC];

__device__ __forceinline__ uint32_t smem_u32(const void* p) {
    uint32_t a;
    asm("{ .reg .u64 t; cvta.to.shared.u64 t, %1; cvt.u32.u64 %0, t; }" : "=r"(a) : "l"(p));
    return a;
}
__device__ __forceinline__ void ldmx4t(uint32_t& r0, uint32_t& r1, uint32_t& r2, uint32_t& r3, uint32_t a) {
    asm volatile("ldmatrix.sync.aligned.m8n8.x4.trans.shared.b16 {%0,%1,%2,%3},[%4];"
                 : "=r"(r0), "=r"(r1), "=r"(r2), "=r"(r3) : "r"(a));
}
__device__ __forceinline__ void ldmx2(uint32_t& r0, uint32_t& r1, uint32_t a) {
    asm volatile("ldmatrix.sync.aligned.m8n8.x2.shared.b16 {%0,%1},[%2];"
                 : "=r"(r0), "=r"(r1) : "r"(a));
}
__device__ __forceinline__ void mma16(float* c, const uint32_t* a, uint32_t b0, uint32_t b1) {
    asm volatile("mma.sync.aligned.m16n8k16.row.col.f32.f16.f16.f32 "
        "{%0,%1,%2,%3},{%4,%5,%6,%7},{%8,%9},{%0,%1,%2,%3};"
        : "+f"(c[0]), "+f"(c[1]), "+f"(c[2]), "+f"(c[3])
        : "r"(a[0]), "r"(a[1]), "r"(a[2]), "r"(a[3]), "r"(b0), "r"(b1));
}
__device__ __forceinline__ uint32_t h2u(__half2 h) { return *reinterpret_cast<uint32_t*>(&h); }

// ---------------------------------------------------------------------------
// prep: bake W into per-lane mma a-fragment order, zero stats.
// ---------------------------------------------------------------------------
__global__ void prep_k(const float* __restrict__ W) {
    int i = blockIdx.x * blockDim.x + threadIdx.x;
    if (i < HH*4*4*32*4) {
        int r    = i & 3;
        int lane = (i >> 2) & 31;
        int kk   = (i >> 7) & 3;
        int w4   = (i >> 9) & 3;
        int h    = i >> 11;
        int grp = lane >> 2, tig = lane & 3;
        int o = w4*16 + grp + (r & 1)*8;
        int c = kk*16 + ((r & 2) ? 8 : 0) + tig*2;
        const float* wp = W + (h*CC + o)*CC + c;
        reinterpret_cast<uint32_t*>(g_Wf)[i] = h2u(__floats2half2_rn(wp[0], wp[1]));
    }
    if (i < 128) g_stats[i] = 0.f;
}

// ---------------------------------------------------------------------------
// conv: fp16 mma.m16n8k16, fp32 accum. CTA = (n, 8 t's), 128 thr, 4 CTAs/SM.
// Identical compute to R12; epilogue = branchless aligned half2 stores into
// 64B-padded rows (pad cols v=25..31 are exact zeros from A smem padding).
// ---------------------------------------------------------------------------
__global__ __launch_bounds__(128, 4) void conv_mma(const float* __restrict__ x,
                                                   const float* __restrict__ A) {
    extern __shared__ char sm[];
    __half* Xh = (__half*)(sm + XH_B);
    __half* Ah = (__half*)(sm + AH_B);
    float*  St = (float*)(sm + ST_B);

    const uint32_t smb = smem_u32(sm);
    const int tid  = threadIdx.x;
    const int warp = tid >> 5, lane = tid & 31;
    const int grp  = lane >> 2, tig = lane & 3;
    const int n    = blockIdx.x >> 6;            // 64 t-blocks per n
    const int t0   = (blockIdx.x & 63) * TB;

    St[tid] = 0.f;

    // --- A smem: [3*32][40] halves, zero-padded beyond 25x25 ---
    for (int i = tid; i < HH*32*32; i += 128) {
        int h = i >> 10, rem = i & 1023;
        int v = rem >> 5, u = rem & 31;
        float val = (v < VV && u < VV) ? A[(h*VV + v)*VV + u] : 0.f;
        Ah[(h*32 + v)*40 + u] = __float2half_rn(val);
    }
    // --- X pad: cols 32t+25..32t+31 zero, all 64 rows ---
    for (int i = tid; i < 64*56; i += 128) {
        int r = i / 56, k = i - r*56;
        int col = 32*(k/7) + 25 + (k%7);
        Xh[r*XS + col] = __float2half(0.f);
    }
    // --- X fill natural: Xh[c][32*(s/25) + s%25] from 200 contiguous floats/c ---
    {
        const float4* x4 = reinterpret_cast<const float4*>(x);
        for (int i = tid; i < CC*50; i += 128) {
            int c = i / 50, q = i - c*50;
            unsigned base = ((unsigned)(n*CC + c)*TT + t0)*VV;   // divisible by 4
            float4 v = x4[(base >> 2) + q];
            float vv[4] = {v.x, v.y, v.z, v.w};
            #pragma unroll
            for (int e = 0; e < 4; ++e) {
                int s = q*4 + e;
                int col = (s/25)*32 + (s - (s/25)*25);
                Xh[c*XS + col] = __float2half_rn(vv[e]);
            }
        }
    }
    __syncthreads();

    // ldmatrix address components
    const int q4 = lane >> 3, r8 = lane & 7;
    const int brow = lane & 7;
    const int bcol8 = (lane & 8) ? 8 : 0;
    const uint32_t xlane = (uint32_t)((r8 + ((q4 & 1) ? 8 : 0)) * XS + ((q4 & 2) ? 8 : 0)) * 2;

    const uint4* wbase = g_Wf + warp*4*32 + lane;

    float st1a = 0.f, st2a = 0.f, st1b = 0.f, st2b = 0.f;
    const int r0 = warp*16 + grp, r1 = r0 + 8;

    for (int t = 0; t < TB; ++t) {
        // ---- X b-fragments for this t (32 regs) ----
        uint32_t xf[4][2][4];
        #pragma unroll
        for (int kk = 0; kk < 4; ++kk)
            #pragma unroll
            for (int jp = 0; jp < 2; ++jp) {
                uint32_t off = xlane + (uint32_t)((16*kk)*XS + 32*t + 16*jp) * 2;
                ldmx4t(xf[kk][jp][0], xf[kk][jp][1], xf[kk][jp][2], xf[kk][jp][3],
                       smb + XH_B + off);
            }

        float OUT[4][4];
        #pragma unroll
        for (int nv = 0; nv < 4; ++nv)
            #pragma unroll
            for (int e = 0; e < 4; ++e) OUT[nv][e] = 0.f;

        #pragma unroll
        for (int h = 0; h < HH; ++h) {
            uint32_t B2[4][2][2];
            #pragma unroll
            for (int nv = 0; nv < 4; ++nv)
                #pragma unroll
                for (int kp = 0; kp < 2; ++kp) {
                    uint32_t off = (uint32_t)(((h*32 + 8*nv + brow)*40) + kp*16 + bcol8) * 2;
                    ldmx2(B2[nv][kp][0], B2[nv][kp][1], smb + AH_B + off);
                }

            // stage 1
            float Y[4][4];
            #pragma unroll
            for (int j = 0; j < 4; ++j)
                #pragma unroll
                for (int e = 0; e < 4; ++e) Y[j][e] = 0.f;

            #pragma unroll
            for (int kk = 0; kk < 4; ++kk) {
                uint4 wv = __ldg(wbase + (h*16 + kk)*32);
                uint32_t whf[4] = {wv.x, wv.y, wv.z, wv.w};
                #pragma unroll
                for (int j = 0; j < 4; ++j) {
                    int jp = j >> 1, ix = (j & 1) * 2;
                    mma16(Y[j], whf, xf[kk][jp][ix], xf[kk][jp][ix + 1]);
                }
            }

            // stage 2
            #pragma unroll
            for (int kp = 0; kp < 2; ++kp) {
                uint32_t ah[4];
                #pragma unroll
                for (int i = 0; i < 4; ++i) {
                    const float* yp = Y[2*kp + (i >> 1)];
                    float p  = yp[(i & 1) ? 2 : 0];
                    float qv = yp[(i & 1) ? 3 : 1];
                    ah[i] = h2u(__floats2half2_rn(p, qv));
                }
                #pragma unroll
                for (int nv = 0; nv < 4; ++nv)
                    mma16(OUT[nv], ah, B2[nv][kp][0], B2[nv][kp][1]);
            }
        }

        // ---- branchless epilogue: aligned half2 stores into 64B rows ----
        unsigned rowA = ((unsigned)(n*CC + r0)*TT + t0 + t);
        unsigned rowB = ((unsigned)(n*CC + r1)*TT + t0 + t);
        #pragma unroll
        for (int nv = 0; nv < 4; ++nv) {
            int p2 = (8*nv + 2*tig) >> 1;       // half2 slot within row
            float a0 = OUT[nv][0], a1 = OUT[nv][1];
            float b0 = OUT[nv][2], b1 = OUT[nv][3];
            g_convP[rowA*16 + p2] = __floats2half2_rn(a0, a1);
            g_convP[rowB*16 + p2] = __floats2half2_rn(b0, b1);
            // pad cols are exact zeros -> contribute 0 to stats
            st1a += a0 + a1; st2a += a0*a0 + a1*a1;
            st1b += b0 + b1; st2b += b0*b0 + b1*b1;
        }
    }

    // --- stats: smem reduce, one global atomic per tid ---
    atomicAdd(&St[r0],      st1a);
    atomicAdd(&St[64 + r0], st2a);
    atomicAdd(&St[r1],      st1b);
    atomicAdd(&St[64 + r1], st2b);
    __syncthreads();
    atomicAdd(&g_stats[tid], St[tid]);
}

// ---------------------------------------------------------------------------
__global__ void stats_k(const float* __restrict__ gamma, const float* __restrict__ beta) {
    int o = threadIdx.x;
    if (o < CC) {
        const float inv = 1.f / (float)CNT_F;
        float mean = g_stats[o] * inv;
        float var  = g_stats[64 + o] * inv - mean*mean;
        float sc = gamma[o] * rsqrtf(var + 1e-5f);
        g_scale[o] = sc;
        g_shift[o] = beta[o] - mean*sc;
    }
}

// ---------------------------------------------------------------------------
// pass 2: out = relu(scale[c]*convP + shift[c] + x); convP rows padded to 32.
// dense g = 4i; row = g/25, v = g%25; per-element wrap to next row (same c:
// a float4 never crosses a channel since 12800 % 4 == 0).
// ---------------------------------------------------------------------------
__global__ void bn_apply(const float4* __restrict__ xv, float4* __restrict__ ov) {
    const __half* ch = reinterpret_cast<const __half*>(g_convP);
    const int n4 = TOTAL / 4;
    int stride = gridDim.x * blockDim.x;
    for (int i = blockIdx.x * blockDim.x + threadIdx.x; i < n4; i += stride) {
        unsigned g = (unsigned)i * 4u;
        unsigned q = g / 25u;
        int v = (int)(g - q*25u);
        int c = (q >> 9) & 63;
        float s  = __ldg(&g_scale[c]);
        float sh = __ldg(&g_shift[c]);
        float4 b = xv[i];
        float f[4];
        #pragma unroll
        for (int e = 0; e < 4; ++e) {
            int ve = v + e;
            int w = (ve >= VV) ? 1 : 0;
            f[e] = __half2float(__ldg(ch + (q + w)*32u + (ve - VV*w)));
        }
        float4 r;
        r.x = fmaxf(fmaf(s, f[0], sh) + b.x, 0.f);
        r.y = fmaxf(fmaf(s, f[1], sh) + b.y, 0.f);
        r.z = fmaxf(fmaf(s, f[2], sh) + b.z, 0.f);
        r.w = fmaxf(fmaf(s, f[3], sh) + b.w, 0.f);
        ov[i] = r;
    }
}

// ---------------------------------------------------------------------------
extern "C" void kernel_launch(void* const* d_in, const int* in_sizes, int n_in,
                              void* d_out, int out_size) {
    const float* x     = (const float*)d_in[0];
    const float* A     = (const float*)d_in[1];
    const float* W     = (const float*)d_in[2];
    // d_in[3] = b : cancels exactly under training-mode BatchNorm -> unused
    const float* gamma = (const float*)d_in[4];
    const float* beta  = (const float*)d_in[5];
    float* out = (float*)d_out;

    cudaFuncSetAttribute(conv_mma, cudaFuncAttributeMaxDynamicSharedMemorySize, SM_BYTES);

    prep_k<<<48, 256>>>(W);
    conv_mma<<<NN*(TT/TB), 128, SM_BYTES>>>(x, A);
    stats_k<<<1, 64>>>(gamma, beta);
    bn_apply<<<4096, 256>>>(reinterpret_cast<const float4*>(x),
                            reinterpret_cast<float4*>(out));
}